// round 2
// baseline (speedup 1.0000x reference)
#include <cuda_runtime.h>
#include <cuda_fp16.h>
#include <stdint.h>

#define H      2048
#define FOURH  8192
#define TSEQ   2048
#define FUT    128
#define TOT    (TSEQ + FUT)
#define NB     148
#define NT     1024

#define GATE_STRIDE ((size_t)2048 * (size_t)H)

// ---------------- persistent device state ----------------
__device__ __align__(16) __half g_w1 [(size_t)FOURH * H];
__device__ __align__(16) __half g_w2i[(size_t)FOURH * H];
__device__ __align__(16) __half g_w2h[(size_t)FOURH * H];
__device__ float  g_b1[FOURH];
__device__ float  g_b2[FOURH];
__device__ __align__(16) float g_h1[2][H];
__device__ __align__(16) float g_h2[2][H];
__device__ float  g_part[NB];
__device__ unsigned g_flags[NB];

// ---------------- prep ----------------
__global__ void prep_kernel(const float* __restrict__ w_hh1,
                            const float* __restrict__ w_ih2,
                            const float* __restrict__ w_hh2,
                            const float* __restrict__ b_ih1,
                            const float* __restrict__ b_hh1,
                            const float* __restrict__ b_ih2,
                            const float* __restrict__ b_hh2)
{
    const size_t n = (size_t)FOURH * H;
    const size_t stride = (size_t)gridDim.x * blockDim.x;
    size_t i0 = (size_t)blockIdx.x * blockDim.x + threadIdx.x;
    for (size_t k = i0; k < n; k += stride) {
        g_w1 [k] = __float2half_rn(w_hh1[k]);
        g_w2i[k] = __float2half_rn(w_ih2[k]);
        g_w2h[k] = __float2half_rn(w_hh2[k]);
    }
    if (i0 < FOURH) {
        g_b1[i0] = b_ih1[i0] + b_hh1[i0];
        g_b2[i0] = b_ih2[i0] + b_hh2[i0];
    }
    if (i0 < NB) g_flags[i0] = 0u;
}

// ---------------- flag-array grid barrier ----------------
__device__ __forceinline__ void grid_sync(int b, int tid, unsigned& target)
{
    ++target;
    __syncthreads();
    if (tid == 0)
        asm volatile("st.release.gpu.u32 [%0], %1;" :: "l"(g_flags + b), "r"(target) : "memory");
    if (tid < NB) {
        unsigned v;
        do {
            asm volatile("ld.acquire.gpu.u32 %0, [%1];" : "=r"(v) : "l"(g_flags + tid) : "memory");
        } while (v < target);
    }
    __syncthreads();
}

__device__ __forceinline__ float sigf(float x) { return 1.0f / (1.0f + __expf(-x)); }

// weight load with L2 evict-last policy
__device__ __forceinline__ uint4 ldw(const __half* p, uint64_t pol)
{
    uint4 v;
    asm volatile("ld.global.nc.L2::cache_hint.v4.u32 {%0,%1,%2,%3}, [%4], %5;"
                 : "=r"(v.x), "=r"(v.y), "=r"(v.z), "=r"(v.w)
                 : "l"(p), "l"(pol));
    return v;
}

__device__ __forceinline__ void fma8(const uint4& wv, const float4& ha, const float4& hb, float& a)
{
    const float2 f0 = __half22float2(*reinterpret_cast<const __half2*>(&wv.x));
    const float2 f1 = __half22float2(*reinterpret_cast<const __half2*>(&wv.y));
    const float2 f2 = __half22float2(*reinterpret_cast<const __half2*>(&wv.z));
    const float2 f3 = __half22float2(*reinterpret_cast<const __half2*>(&wv.w));
    a = fmaf(f0.x, ha.x, a); a = fmaf(f0.y, ha.y, a);
    a = fmaf(f1.x, ha.z, a); a = fmaf(f1.y, ha.w, a);
    a = fmaf(f2.x, hb.x, a); a = fmaf(f2.y, hb.y, a);
    a = fmaf(f3.x, hb.z, a); a = fmaf(f3.y, hb.w, a);
}

// 4-gate dot over 1024 elements with double-buffered loads; pre[] holds m=0 loads.
__device__ __forceinline__ void dot4_pre(const __half* __restrict__ w, const float* hs,
                                         int lane, float acc[4], uint4 pre[4], uint64_t pol)
{
    acc[0] = acc[1] = acc[2] = acc[3] = 0.0f;
    uint4 buf[4];
    #pragma unroll
    for (int m = 0; m < 4; ++m) {
        if (m < 3) {
            #pragma unroll
            for (int g = 0; g < 4; ++g)
                buf[g] = ldw(w + (size_t)g * GATE_STRIDE + (m + 1) * 256 + lane * 8, pol);
        }
        const int base = m * 256 + lane * 8;
        const float4 ha = *reinterpret_cast<const float4*>(hs + base);
        const float4 hb = *reinterpret_cast<const float4*>(hs + base + 4);
        #pragma unroll
        for (int g = 0; g < 4; ++g) fma8(pre[g], ha, hb, acc[g]);
        #pragma unroll
        for (int g = 0; g < 4; ++g) pre[g] = buf[g];
    }
}

__device__ __forceinline__ void reduce4(float acc[4])
{
    #pragma unroll
    for (int g = 0; g < 4; ++g) {
        #pragma unroll
        for (int o = 16; o > 0; o >>= 1)
            acc[g] += __shfl_xor_sync(0xffffffffu, acc[g], o);
    }
}

// ---------------- main persistent kernel ----------------
__global__ void __launch_bounds__(NT, 1)
lstm_main(const float* __restrict__ input,
          const float* __restrict__ w_ih1,
          const float* __restrict__ w_lin,
          const float* __restrict__ b_lin,
          float* __restrict__ out)
{
    const int b    = blockIdx.x;
    const int tid  = threadIdx.x;
    const int warp = tid >> 5;
    const int lane = tid & 31;
    const int nI   = (H - b + NB - 1) / NB;   // 14 or 13

    __shared__ __align__(16) float s_h[2 * H];
    __shared__ float s_g1[14][4][2];
    __shared__ float s_g2[14][4][4];
    __shared__ float s_c1[14], s_c2[14], s_o[14];
    __shared__ float s_bcast;

    uint64_t pol;
    asm("createpolicy.fractional.L2::evict_last.b64 %0, 1.0;" : "=l"(pol));

    unsigned target = 0;

    // layer-1 task (fixed per warp for whole run)
    const bool  t1   = (warp < nI * 2);
    const int   i1   = warp >> 1;
    const int   kh1  = warp & 1;
    const int   j1   = b + i1 * NB;
    const __half* w1p = g_w1 + (size_t)j1 * H + kh1 * (H / 2);

    // layer-2 tasks
    const int tA = warp;                // always < nI*4 (>= 52)
    const int tB = warp + 32;
    const int iA = tA >> 2, subA = tA & 3, srcA = subA >> 1, khA = subA & 1;
    const __half* wAp = (srcA ? g_w2h : g_w2i) + (size_t)(b + iA * NB) * H + khA * (H / 2);
    const bool  tBv = (tB < nI * 4);
    const int iB = tB >> 2, subB = tB & 3, srcB = subB >> 1, khB = subB & 1;
    const __half* wBp = (srcB ? g_w2h : g_w2i) + (size_t)(b + iB * NB) * H + khB * (H / 2);

    // init state
    if (tid < nI) {
        const int j = b + tid * NB;
        s_c1[tid] = 0.0f; s_c2[tid] = 0.0f;
        g_h1[0][j] = 0.0f; g_h1[1][j] = 0.0f;
        g_h2[0][j] = 0.0f; g_h2[1][j] = 0.0f;
    }
    grid_sync(b, tid, target);

    const float blin = __ldg(b_lin);

    // prefetch layer-1 m=0 for t=0
    uint4 pre1[4];
    if (t1) {
        #pragma unroll
        for (int g = 0; g < 4; ++g) pre1[g] = ldw(w1p + (size_t)g * GATE_STRIDE + lane * 8, pol);
    }

    for (int t = 0; t < TOT; ++t) {
        const int cur  = t & 1;
        const int prev = cur ^ 1;

        // ---- stage h1(prev) (float4, L2-coherent) ----
        if (tid < H / 4)
            *reinterpret_cast<float4*>(s_h + 4 * tid) =
                __ldcg(reinterpret_cast<const float4*>(&g_h1[prev][4 * tid]));
        __syncthreads();   // also publishes s_bcast from previous step tail

        // ---- layer-1 dots ----
        if (t1) {
            float acc[4];
            dot4_pre(w1p, s_h + kh1 * (H / 2), lane, acc, pre1, pol);
            reduce4(acc);
            if (lane == 0) {
                s_g1[i1][0][kh1] = acc[0]; s_g1[i1][1][kh1] = acc[1];
                s_g1[i1][2][kh1] = acc[2]; s_g1[i1][3][kh1] = acc[3];
            }
        }
        __syncthreads();

        // ---- layer-1 elementwise ----
        if (tid < nI) {
            const float x = (t < TSEQ) ? __ldg(input + t) : s_bcast;
            const int j = b + tid * NB;
            const float gi = s_g1[tid][0][0] + s_g1[tid][0][1] + g_b1[j]        + __ldg(w_ih1 + j)        * x;
            const float gf = s_g1[tid][1][0] + s_g1[tid][1][1] + g_b1[j + 2048] + __ldg(w_ih1 + j + 2048) * x;
            const float gg = s_g1[tid][2][0] + s_g1[tid][2][1] + g_b1[j + 4096] + __ldg(w_ih1 + j + 4096) * x;
            const float go = s_g1[tid][3][0] + s_g1[tid][3][1] + g_b1[j + 6144] + __ldg(w_ih1 + j + 6144) * x;
            const float c  = sigf(gf) * s_c1[tid] + sigf(gi) * tanhf(gg);
            s_c1[tid] = c;
            g_h1[cur][j] = sigf(go) * tanhf(c);
        }

        // prefetch layer-2 task A m=0 (overlaps barrier)
        uint4 preA[4];
        #pragma unroll
        for (int g = 0; g < 4; ++g) preA[g] = ldw(wAp + (size_t)g * GATE_STRIDE + lane * 8, pol);

        grid_sync(b, tid, target);

        // ---- stage h1(cur) | h2(prev) ----
        {
            const int q = tid;  // 1024 threads, 1024 float4 = 4096 floats
            if (q < 512)
                *reinterpret_cast<float4*>(s_h + 4 * q) =
                    __ldcg(reinterpret_cast<const float4*>(&g_h1[cur][4 * q]));
            else
                *reinterpret_cast<float4*>(s_h + 4 * q) =
                    __ldcg(reinterpret_cast<const float4*>(&g_h2[prev][4 * (q - 512)]));
        }
        __syncthreads();

        // ---- layer-2 dots: task A then (maybe) task B ----
        {
            float acc[4];
            dot4_pre(wAp, s_h + srcA * H + khA * (H / 2), lane, acc, preA, pol);
            reduce4(acc);
            if (lane == 0) {
                s_g2[iA][0][subA] = acc[0]; s_g2[iA][1][subA] = acc[1];
                s_g2[iA][2][subA] = acc[2]; s_g2[iA][3][subA] = acc[3];
            }
        }
        if (tBv) {
            uint4 preB[4];
            #pragma unroll
            for (int g = 0; g < 4; ++g) preB[g] = ldw(wBp + (size_t)g * GATE_STRIDE + lane * 8, pol);
            float acc[4];
            dot4_pre(wBp, s_h + srcB * H + khB * (H / 2), lane, acc, preB, pol);
            reduce4(acc);
            if (lane == 0) {
                s_g2[iB][0][subB] = acc[0]; s_g2[iB][1][subB] = acc[1];
                s_g2[iB][2][subB] = acc[2]; s_g2[iB][3][subB] = acc[3];
            }
        }
        __syncthreads();

        // ---- layer-2 elementwise ----
        if (tid < nI) {
            const int j = b + tid * NB;
            const float gi = s_g2[tid][0][0] + s_g2[tid][0][1] + s_g2[tid][0][2] + s_g2[tid][0][3] + g_b2[j];
            const float gf = s_g2[tid][1][0] + s_g2[tid][1][1] + s_g2[tid][1][2] + s_g2[tid][1][3] + g_b2[j + 2048];
            const float gg = s_g2[tid][2][0] + s_g2[tid][2][1] + s_g2[tid][2][2] + s_g2[tid][2][3] + g_b2[j + 4096];
            const float go = s_g2[tid][3][0] + s_g2[tid][3][1] + s_g2[tid][3][2] + s_g2[tid][3][3] + g_b2[j + 6144];
            const float c  = sigf(gf) * s_c2[tid] + sigf(gi) * tanhf(gg);
            s_c2[tid] = c;
            const float h = sigf(go) * tanhf(c);
            g_h2[cur][j] = h;
            s_o[tid] = h * __ldg(w_lin + j);
        }
        __syncthreads();
        if (tid == 0) {
            float s = 0.0f;
            #pragma unroll
            for (int i = 0; i < 14; ++i) if (i < nI) s += s_o[i];
            g_part[b] = s;
        }

        // prefetch layer-1 m=0 for NEXT step (overlaps barrier + reduce)
        if (t1) {
            #pragma unroll
            for (int g = 0; g < 4; ++g) pre1[g] = ldw(w1p + (size_t)g * GATE_STRIDE + lane * 8, pol);
        }

        grid_sync(b, tid, target);

        // ---- scalar output reduce (warp 0, overlapped with next step's staging) ----
        if (warp == 0) {
            float s = 0.0f;
            #pragma unroll
            for (int p = lane; p < NB; p += 32) s += __ldcg(&g_part[p]);
            #pragma unroll
            for (int o = 16; o > 0; o >>= 1) s += __shfl_xor_sync(0xffffffffu, s, o);
            if (lane == 0) {
                const float y = s + blin;
                s_bcast = y;                       // published by next step's first __syncthreads
                if (b == 0) out[t] = y;
            }
        }
    }
}

// ---------------- launch ----------------
extern "C" void kernel_launch(void* const* d_in, const int* in_sizes, int n_in,
                              void* d_out, int out_size)
{
    const float* input = (const float*)d_in[0];
    const float* w_ih1 = (const float*)d_in[1];
    const float* w_hh1 = (const float*)d_in[2];
    const float* b_ih1 = (const float*)d_in[3];
    const float* b_hh1 = (const float*)d_in[4];
    const float* w_ih2 = (const float*)d_in[5];
    const float* w_hh2 = (const float*)d_in[6];
    const float* b_ih2 = (const float*)d_in[7];
    const float* b_hh2 = (const float*)d_in[8];
    const float* w_lin = (const float*)d_in[9];
    const float* b_lin = (const float*)d_in[10];
    float* out = (float*)d_out;

    prep_kernel<<<1024, 256>>>(w_hh1, w_ih2, w_hh2, b_ih1, b_hh1, b_ih2, b_hh2);
    lstm_main<<<NB, NT>>>(input, w_ih1, w_lin, b_lin, out);
}